// round 16
// baseline (speedup 1.0000x reference)
#include <cuda_runtime.h>
#include <cstdint>
#include <math.h>

#define BATCH 8
#define NPTS  4096
#define M1    2048
#define M2    512
#define KNB   64
#define TIE_CAP 128

typedef unsigned long long u64;

// ----------------------------------------------------------------------------
// Scratch (device globals; no allocations allowed)
// ----------------------------------------------------------------------------
static __device__ __align__(16) float    g_cent1[BATCH * M1 * 3];
static __device__ int      g_nbr1 [BATCH * M1 * KNB];
static __device__ int      g_cnt1 [BATCH * M1];
static __device__ __align__(16) float    g_x1   [BATCH * M1 * 64];
static __device__ __align__(16) float    g_cent2[BATCH * M2 * 3];
static __device__ int      g_nbr2 [BATCH * M2 * KNB];
static __device__ int      g_cnt2 [BATCH * M2];
static __device__ __align__(16) float    g_x2   [BATCH * M2 * 128];
static __device__ unsigned g_featEnc[BATCH * 512];
// FPS chunk-resume state
static __device__ float    g_fpsld[BATCH * 512 * 8];
static __device__ int      g_fpsfidx[BATCH];

// ----------------------------------------------------------------------------
// Helpers
// ----------------------------------------------------------------------------
__device__ __forceinline__ float d2_ref(float dx, float dy, float dz) {
    // XLA-style fused emission of sum((p-c)**2) over size-3 axis
    return __fmaf_rn(dz, dz, __fmaf_rn(dy, dy, __fmul_rn(dx, dx)));
}

__device__ __forceinline__ unsigned encf(float f) {
    unsigned u = __float_as_uint(f);
    return (u & 0x80000000u) ? ~u : (u | 0x80000000u);
}
__device__ __forceinline__ float decf(unsigned u) {
    return (u & 0x80000000u) ? __uint_as_float(u & 0x7FFFFFFFu) : __uint_as_float(~u);
}

// packed f32x2 FMA: acc = a*b + acc (two independent IEEE fp32 FMAs)
__device__ __forceinline__ void ffma2(u64& acc, u64 a, u64 b) {
    asm("fma.rn.f32x2 %0, %1, %2, %0;" : "+l"(acc) : "l"(a), "l"(b));
}
__device__ __forceinline__ u64 bcast2(float f) {
    u64 r;
    asm("mov.b64 %0, {%1, %1};" : "=l"(r) : "f"(f));
    return r;
}
__device__ __forceinline__ void unpack2(u64 p, float& lo, float& hi) {
    asm("mov.b64 {%0, %1}, %2;" : "=f"(lo), "=f"(hi) : "l"(p));
}

// ----------------------------------------------------------------------------
// FPS: one block (512 thr) per batch. REDUX-based argmax, one barrier/iter.
// Chunked: iterations [t0,t1); running-min state persisted in g_fpsld/g_fpsfidx
// across chunks (bit-identical continuation of the monolithic loop).
// ----------------------------------------------------------------------------
__global__ void fps_kernel(const float* __restrict__ pos_ext, int level, int N, int M,
                           int t0, int t1)
{
    extern __shared__ float spos[];  // N*3 floats
    __shared__ u64 wred[2][16];

    const float* srcbase = (level == 0) ? pos_ext : g_cent1;
    float* cent_out      = (level == 0) ? g_cent1 : g_cent2;

    const int b = blockIdx.x, tid = threadIdx.x;
    const int nt = 512;
    const float* P = srcbase + (size_t)b * N * 3;
    for (int i = tid; i < N * 3; i += nt) spos[i] = P[i];
    __syncthreads();

    float lx[8], ly[8], lz[8], ld[8];
    const int KP = N / nt;              // 8 (level0) or 4 (level1)
    #pragma unroll
    for (int k = 0; k < 8; ++k) {
        if (k < KP) {
            int p = tid + k * nt;
            lx[k] = spos[p*3]; ly[k] = spos[p*3+1]; lz[k] = spos[p*3+2];
        }
        ld[k] = __int_as_float(0x7f800000);  // +inf
    }

    int fidx = 0;
    if (t0 > 0) {
        const float* st = g_fpsld + ((size_t)b * 512 + tid) * 8;
        #pragma unroll
        for (int k = 0; k < 8; ++k) if (k < KP) ld[k] = st[k];
        fidx = g_fpsfidx[b];
    }

    const int lane = tid & 31, warp = tid >> 5;

    for (int t = t0; t < t1; ++t) {
        float cx = spos[fidx*3], cy = spos[fidx*3+1], cz = spos[fidx*3+2];
        if (tid == 0) {
            int o = (b * M + t) * 3;
            cent_out[o] = cx; cent_out[o+1] = cy; cent_out[o+2] = cz;
        }
        unsigned bb = 0u; int bi = 0;
        #pragma unroll
        for (int k = 0; k < 8; ++k) {
            if (k < KP) {
                int p = tid + k * nt;
                float d  = d2_ref(lx[k]-cx, ly[k]-cy, lz[k]-cz);
                float nd = fminf(ld[k], d);
                ld[k] = nd;
                unsigned bits = __float_as_uint(nd);   // nd >= 0 -> uint order == float order
                if (bits > bb) { bb = bits; bi = p; }  // ascending p -> min idx on tie
            }
        }
        unsigned m    = __reduce_max_sync(0xFFFFFFFFu, bb);
        unsigned cand = (bb == m) ? (unsigned)bi : 0xFFFFFFFFu;
        unsigned widx = __reduce_min_sync(0xFFFFFFFFu, cand);
        if (lane == 0) wred[t & 1][warp] = (((u64)m) << 32) | widx;
        __syncthreads();
        u64 kk = (lane < 16) ? wred[t & 1][lane] : 0ULL;
        unsigned hi = (unsigned)(kk >> 32), lo = (unsigned)kk;
        unsigned m2    = __reduce_max_sync(0xFFFFFFFFu, hi);
        unsigned cand2 = (hi == m2) ? lo : 0xFFFFFFFFu;
        fidx = (int)__reduce_min_sync(0xFFFFFFFFu, cand2);
    }

    if (t1 < M) {
        float* st = g_fpsld + ((size_t)b * 512 + tid) * 8;
        #pragma unroll
        for (int k = 0; k < 8; ++k) if (k < KP) st[k] = ld[k];
        if (tid == 0) g_fpsfidx[b] = fidx;
    }
}

// ----------------------------------------------------------------------------
// KNN: radius-limited 64 smallest, one block (128 thr) per center.
// float4-vectorized scan + histogram cutoff-selection; bitonic fallback.
// Processes centers [c0, c0+CH) per batch (grid = BATCH*CH).
// Level 1 additionally zeroes g_featEnc[bm].
// ----------------------------------------------------------------------------
struct __align__(16) KnnShared {
    int scnt, osel, tcnt, sT, sN1;
    int hist[256];
    u64 tie[TIE_CAP];
};

__global__ __launch_bounds__(128) void knn_kernel(
    const float* __restrict__ pos_ext, int level, int N, int M, float R2,
    float binscale, int CAP, int c0, int CH)
{
    extern __shared__ u64 keys[];  // CAP entries
    __shared__ KnnShared S;

    const float* pts     = (level == 0) ? pos_ext : g_cent1;
    const float* centers = (level == 0) ? g_cent1 : g_cent2;
    int* nbr             = (level == 0) ? g_nbr1  : g_nbr2;
    int* cnt             = (level == 0) ? g_cnt1  : g_cnt2;

    const int b  = blockIdx.x / CH;
    const int bm = b * M + c0 + (blockIdx.x - b * CH);
    const int tid = threadIdx.x, nt = 128;
    if (level == 1 && tid == 0) g_featEnc[bm] = 0u;

    const float* P = pts + (size_t)b * N * 3;
    const float cx = centers[bm*3], cy = centers[bm*3+1], cz = centers[bm*3+2];

    if (tid == 0) { S.scnt = 0; S.osel = 0; S.tcnt = 0; }
    for (int i = tid; i < 256; i += nt) S.hist[i] = 0;
    __syncthreads();

    // vectorized scan: 4 points per thread-iteration via 3x LDG.128
    const float4* P4 = reinterpret_cast<const float4*>(P);
    const int NG = N >> 2;
    for (int g = tid; g < NG; g += nt) {
        float4 A = __ldg(P4 + g*3 + 0);
        float4 B = __ldg(P4 + g*3 + 1);
        float4 Cv = __ldg(P4 + g*3 + 2);
        float px[4] = {A.x, A.w, B.z, Cv.y};
        float py[4] = {A.y, B.x, B.w, Cv.z};
        float pz[4] = {A.z, B.y, Cv.x, Cv.w};
        #pragma unroll
        for (int k = 0; k < 4; ++k) {
            float d2 = d2_ref(px[k]-cx, py[k]-cy, pz[k]-cz);
            if (d2 <= R2) {
                int q = atomicAdd(&S.scnt, 1);
                if (q < CAP) {
                    keys[q] = (((u64)__float_as_uint(d2)) << 32) | (unsigned)(4*g + k);
                    int bin = (int)(d2 * binscale); if (bin > 255) bin = 255;
                    atomicAdd(&S.hist[bin], 1);
                }
            }
        }
    }
    __syncthreads();
    int C = S.scnt; if (C > CAP) C = CAP;
    const int KO = (C < KNB) ? C : KNB;

    if (C <= KNB) {
        for (int k = tid; k < KNB; k += nt)
            nbr[(size_t)bm * KNB + k] = (k < C) ? (int)(unsigned)keys[k] : 0;
        if (tid == 0) cnt[bm] = KO;
        return;
    }

    // cutoff bin T: first bin with cumulative count >= 64
    const int warp = tid >> 5, lane = tid & 31;
    if (warp == 0) {
        int base8 = lane * 8;
        int h[8]; int s = 0;
        #pragma unroll
        for (int k = 0; k < 8; ++k) { h[k] = S.hist[base8 + k]; s += h[k]; }
        int Ssc = s;
        #pragma unroll
        for (int o = 1; o < 32; o <<= 1) {
            int v = __shfl_up_sync(0xFFFFFFFFu, Ssc, o);
            if (lane >= o) Ssc += v;
        }
        unsigned bal = __ballot_sync(0xFFFFFFFFu, Ssc >= KNB);
        int L = __ffs(bal) - 1;
        int Sprev = __shfl_up_sync(0xFFFFFFFFu, Ssc, 1);
        if (lane == L) {
            int cum = (L > 0) ? Sprev : 0;
            int T = base8, n1v = cum;
            #pragma unroll
            for (int k = 0; k < 8; ++k) {
                if (cum + h[k] >= KNB) { T = base8 + k; n1v = cum; break; }
                cum += h[k];
            }
            S.sT = T; S.sN1 = n1v;
        }
    }
    __syncthreads();
    const int T = S.sT, n1 = S.sN1, k2 = KNB - n1;

    for (int q = tid; q < C; q += nt) {
        u64 key = keys[q];
        float d2 = __uint_as_float((unsigned)(key >> 32));
        int bin = (int)(d2 * binscale); if (bin > 255) bin = 255;
        if (bin < T) {
            int o = atomicAdd(&S.osel, 1);
            nbr[(size_t)bm * KNB + o] = (int)(unsigned)key;
        } else if (bin == T) {
            int tq = atomicAdd(&S.tcnt, 1);
            if (tq < TIE_CAP) S.tie[tq] = key;
        }
    }
    __syncthreads();

    if (S.tcnt <= TIE_CAP) {
        const int t = S.tcnt;
        for (int e = tid; e < t; e += nt) {
            u64 me = S.tie[e];
            int rank = 0;
            for (int f = 0; f < t; ++f) rank += (S.tie[f] < me);
            if (rank < k2) nbr[(size_t)bm * KNB + n1 + rank] = (int)(unsigned)me;
        }
    } else {
        // fallback: full bitonic sort (never expected on this data)
        int Pow = 1; while (Pow < C) Pow <<= 1;
        for (int i = C + tid; i < Pow; i += nt) keys[i] = ~0ULL;
        __syncthreads();
        for (int size = 2; size <= Pow; size <<= 1) {
            for (int stride = size >> 1; stride > 0; stride >>= 1) {
                for (int t2 = tid; t2 < (Pow >> 1); t2 += nt) {
                    int lo = (t2 << 1) - (t2 & (stride - 1));
                    int hi = lo + stride;
                    u64 a = keys[lo], c2 = keys[hi];
                    bool asc = ((lo & size) == 0);
                    if ((a > c2) == asc) { keys[lo] = c2; keys[hi] = a; }
                }
                __syncthreads();
            }
        }
        for (int k = tid; k < KNB; k += nt)
            nbr[(size_t)bm * KNB + k] = (int)(unsigned)keys[k];
    }
    if (tid == 0) cnt[bm] = KNB;
}

// ----------------------------------------------------------------------------
// Templated MLP layer on duplicated-pair feature buffers (row-major mapping,
// per-i LDS.64 feature broadcast). Measured-best variant.
// ----------------------------------------------------------------------------
template<int DIN, int DOUT, bool RELUDUP, int R>
__device__ __forceinline__ void mlpD(const u64* __restrict__ Fin, void* __restrict__ Fout,
                                     const float* __restrict__ w, const float* __restrict__ bias,
                                     int rows)
{
    constexpr int JB = DOUT / 4;     // power of two
    const int tid = threadIdx.x;
    const int total = (rows / R) * JB;
    for (int it = tid; it < total; it += 128) {
        const int np = it / JB;
        const int j  = (it - np * JB) << 2;
        const u64* f0 = Fin + (np * R) * DIN;
        ulonglong2 b2 = *reinterpret_cast<const ulonglong2*>(bias + j);
        u64 accL[R], accH[R];
        #pragma unroll
        for (int r = 0; r < R; ++r) { accL[r] = b2.x; accH[r] = b2.y; }
        #pragma unroll 4
        for (int i = 0; i < DIN; ++i) {
            ulonglong2 wv = __ldg(reinterpret_cast<const ulonglong2*>(w + i * DOUT + j));
            #pragma unroll
            for (int r = 0; r < R; ++r) {
                u64 u = f0[r * DIN + i];
                ffma2(accL[r], wv.x, u);
                ffma2(accH[r], wv.y, u);
            }
        }
        if (RELUDUP) {
            u64* out = (u64*)Fout;
            #pragma unroll
            for (int r = 0; r < R; ++r) {
                u64* o = out + (np * R + r) * DOUT + j;
                float x, y;
                unpack2(accL[r], x, y);
                o[0] = bcast2(fmaxf(x, 0.f)); o[1] = bcast2(fmaxf(y, 0.f));
                unpack2(accH[r], x, y);
                o[2] = bcast2(fmaxf(x, 0.f)); o[3] = bcast2(fmaxf(y, 0.f));
            }
        } else {
            float* out = (float*)Fout;
            #pragma unroll
            for (int r = 0; r < R; ++r)
                *reinterpret_cast<ulonglong2*>(out + (np * R + r) * DOUT + j) =
                    make_ulonglong2(accL[r], accH[r]);
        }
    }
}

// ----------------------------------------------------------------------------
// SA1: per-center MLP(3->32->32->64) over 64 neighbors + masked max.
// ----------------------------------------------------------------------------
__global__ __launch_bounds__(128) void sa1_kernel(
    const float* __restrict__ pos,
    const float* __restrict__ w0, const float* __restrict__ b0,
    const float* __restrict__ w1, const float* __restrict__ b1,
    const float* __restrict__ w2, const float* __restrict__ b2)
{
    __shared__ __align__(16) u64 F0[64 * 3];
    __shared__ __align__(16) u64 FA[64 * 32];    // L0 out dup; final plain f32 (64x64)
    __shared__ __align__(16) u64 FB[64 * 32];    // L1 out dup
    const int bm = blockIdx.x;      // b*M1 + m
    const int b  = bm >> 11;
    const int tid = threadIdx.x;
    const int C = g_cnt1[bm];

    if (tid < 64) {
        int n = tid;
        float rx = 0.f, ry = 0.f, rz = 0.f;
        if (n < C) {
            int q = g_nbr1[(size_t)bm * KNB + n];
            const float* pp = pos + ((size_t)b * NPTS + q) * 3;
            rx = pp[0] - g_cent1[bm*3];
            ry = pp[1] - g_cent1[bm*3+1];
            rz = pp[2] - g_cent1[bm*3+2];
        }
        F0[n*3] = bcast2(rx); F0[n*3+1] = bcast2(ry); F0[n*3+2] = bcast2(rz);
    }
    __syncthreads();
    mlpD<3, 32, true, 4>(F0, FA, w0, b0, 64); __syncthreads();
    mlpD<32, 32, true, 4>(FA, FB, w1, b1, 64); __syncthreads();
    mlpD<32, 64, false, 4>(FB, FA, w2, b2, 64); __syncthreads();
    const float* FC = (const float*)FA;
    for (int j = tid; j < 64; j += 128) {
        float m = FC[j];
        for (int n = 1; n < C; ++n) m = fmaxf(m, FC[n*64 + j]);
        g_x1[(size_t)bm * 64 + j] = m;
    }
}

// ----------------------------------------------------------------------------
// SA2: per-center MLP(67->64->64->128) over 64 neighbors + masked max.
// Row-chunked (32 rows).
// ----------------------------------------------------------------------------
__global__ __launch_bounds__(128) void sa2_kernel(
    const float* __restrict__ w0, const float* __restrict__ b0,
    const float* __restrict__ w1, const float* __restrict__ b1,
    const float* __restrict__ w2, const float* __restrict__ b2)
{
    __shared__ __align__(16) u64 bufA[32 * 67];  // in dup (67); L1 out dup (64)
    __shared__ __align__(16) u64 bufB[32 * 64];  // L0 out dup (64); final plain f32 (32x128)
    __shared__ float srel[64 * 3];
    __shared__ int   sq[64];
    const int bm = blockIdx.x;      // b*M2 + m
    const int b  = bm >> 9;
    const int tid = threadIdx.x;
    const int C = g_cnt2[bm];

    if (tid < 64) {
        int n = tid;
        int q = 0; float rx = 0.f, ry = 0.f, rz = 0.f;
        if (n < C) {
            q = g_nbr2[(size_t)bm * KNB + n];
            const float* pp = g_cent1 + ((size_t)b * M1 + q) * 3;
            rx = pp[0] - g_cent2[bm*3];
            ry = pp[1] - g_cent2[bm*3+1];
            rz = pp[2] - g_cent2[bm*3+2];
        }
        sq[n] = q; srel[n*3] = rx; srel[n*3+1] = ry; srel[n*3+2] = rz;
    }
    __syncthreads();

    float m = -__int_as_float(0x7f800000);   // -inf; C >= 1 always
    #pragma unroll
    for (int chunk = 0; chunk < 2; ++chunk) {
        const int r0 = chunk * 32;
        if (r0 >= C) break;
        for (int e = tid; e < 32 * 64; e += 128) {
            int n = e >> 6, i = e & 63;
            int g = r0 + n;
            bufA[n*67 + i] = (g < C) ? bcast2(g_x1[((size_t)b * M1 + sq[g]) * 64 + i]) : 0ULL;
        }
        if (tid < 96) {
            int n = tid / 3, c = tid - n * 3;
            int g = r0 + n;
            bufA[n*67 + 64 + c] = (g < C) ? bcast2(srel[g*3 + c]) : 0ULL;
        }
        __syncthreads();
        mlpD<67, 64, true, 4>(bufA, bufB, w0, b0, 32); __syncthreads();
        mlpD<64, 64, true, 4>(bufB, bufA, w1, b1, 32); __syncthreads();
        mlpD<64, 128, false, 4>(bufA, bufB, w2, b2, 32); __syncthreads();
        const float* FC = (const float*)bufB;
        if (tid < 128) {
            int nv = C - r0; if (nv > 32) nv = 32;
            float mm = m;
            for (int n = 0; n < nv; ++n) mm = fmaxf(mm, FC[n*128 + tid]);
            m = mm;
        }
        __syncthreads();
    }
    g_x2[(size_t)bm * 128 + tid] = m;
}

// ----------------------------------------------------------------------------
// SA3 + global max pool: MLP(131->128->256->512) per point, atomic-max pool.
// ----------------------------------------------------------------------------
__global__ __launch_bounds__(128) void sa3_kernel(
    const float* __restrict__ w0, const float* __restrict__ b0,
    const float* __restrict__ w1, const float* __restrict__ b1,
    const float* __restrict__ w2, const float* __restrict__ b2)
{
    __shared__ __align__(16) u64 bufA[8 * 256];   // in dup (131); L1 out dup (256)
    __shared__ __align__(16) u64 bufB[8 * 256];   // L0 out dup (128); final plain f32 (8x512)
    const int b  = blockIdx.x >> 6;             // 64 blocks per batch
    const int m0 = (blockIdx.x & 63) * 8;
    const int tid = threadIdx.x;

    for (int e = tid; e < 8 * 128; e += 128) {
        int n = e >> 7, i = e & 127;
        bufA[n*131 + i] = bcast2(g_x2[((size_t)b * M2 + m0 + n) * 128 + i]);
    }
    if (tid < 24) {
        int n = tid / 3, c = tid - n * 3;
        bufA[n*131 + 128 + c] = bcast2(g_cent2[((size_t)b * M2 + m0 + n) * 3 + c]);
    }
    __syncthreads();
    mlpD<131, 128, true, 2>(bufA, bufB, w0, b0, 8); __syncthreads();
    mlpD<128, 256, true, 4>(bufB, bufA, w1, b1, 8); __syncthreads();
    mlpD<256, 512, false, 4>(bufA, bufB, w2, b2, 8); __syncthreads();
    const float* FC = (const float*)bufB;
    for (int j = tid; j < 512; j += 128) {
        float m = FC[j];
        #pragma unroll
        for (int n = 1; n < 8; ++n) m = fmaxf(m, FC[n*512 + j]);
        atomicMax(&g_featEnc[b * 512 + j], encf(m));
    }
}

// ----------------------------------------------------------------------------
// Head: mu/logvar linear + reparameterization (partitionable threefry).
// ----------------------------------------------------------------------------
__device__ __forceinline__ uint32_t rotl32(uint32_t x, int r) { return (x << r) | (x >> (32 - r)); }

__device__ __forceinline__ void threefry2x32(uint32_t k0, uint32_t k1, uint32_t& x0, uint32_t& x1)
{
    uint32_t ks0 = k0, ks1 = k1, ks2 = k0 ^ k1 ^ 0x1BD11BDAu;
    const int R0[4] = {13, 15, 26, 6};
    const int R1[4] = {17, 29, 16, 24};
    x0 += ks0; x1 += ks1;
    #pragma unroll
    for (int i = 0; i < 5; ++i) {
        #pragma unroll
        for (int rr = 0; rr < 4; ++rr) {
            int r = (i & 1) ? R1[rr] : R0[rr];
            x0 += x1; x1 = rotl32(x1, r); x1 ^= x0;
        }
        uint32_t a = (i % 3 == 0) ? ks1 : ((i % 3 == 1) ? ks2 : ks0);
        uint32_t c = (i % 3 == 0) ? ks2 : ((i % 3 == 1) ? ks0 : ks1);
        x0 += a; x1 += c + (uint32_t)(i + 1);
    }
}

__global__ void head_kernel(const float* __restrict__ w_mu, const float* __restrict__ b_mu,
                            const float* __restrict__ w_lv, const float* __restrict__ b_lv,
                            float* __restrict__ out)
{
    __shared__ float feat[512];
    const int b = blockIdx.x, tid = threadIdx.x;  // 32 threads
    for (int i = tid; i < 512; i += 32) feat[i] = decf(g_featEnc[b * 512 + i]);
    __syncthreads();

    const int j = tid;
    float mu = __ldg(b_mu + j), lv = __ldg(b_lv + j);
    #pragma unroll 4
    for (int i = 0; i < 512; ++i) {
        float f = feat[i];
        mu = fmaf(f, __ldg(w_mu + i * 32 + j), mu);
        lv = fmaf(f, __ldg(w_lv + i * 32 + j), lv);
    }

    int e = b * 32 + j;
    uint32_t x0 = 0u, x1 = (uint32_t)e;
    threefry2x32(0u, 42u, x0, x1);
    uint32_t y = x0 ^ x1;

    float u01 = __uint_as_float((y >> 9) | 0x3F800000u) - 1.0f;
    const float lo = -0.99999994f;
    float u = fmaxf(lo, __fmaf_rn(u01, 2.0f, lo));
    float eps = 1.41421356f * erfinvf(u);

    float z = mu + eps * expf(0.5f * lv);
    out[b * 32 + j]        = z;
    out[256 + b * 32 + j]  = mu;
    out[512 + b * 32 + j]  = lv;
}

// ----------------------------------------------------------------------------
// Launch (pipelined fps0 / knn0):
//   s0:  fps0[0:512] e0 | fps0[512:1024] e1 | fps0[1024:1536] e2 | fps0[1536:2048] e3
//   s1:  (wait e_k) knn0 chunk k, k=0..3  -> eK
//   s2:  (wait e3) fps1 -> knn1 -> eL       (knn1 zeroes g_featEnc)
//   s0:  wait eK -> sa1 ; wait eL -> sa2 -> sa3 -> head
// ----------------------------------------------------------------------------
extern "C" void kernel_launch(void* const* d_in, const int* in_sizes, int n_in,
                              void* d_out, int out_size)
{
    (void)in_sizes; (void)n_in; (void)out_size;
    const float* pos  = (const float*)d_in[0];
    const float* s1w0 = (const float*)d_in[1];  const float* s1b0 = (const float*)d_in[2];
    const float* s1w1 = (const float*)d_in[3];  const float* s1b1 = (const float*)d_in[4];
    const float* s1w2 = (const float*)d_in[5];  const float* s1b2 = (const float*)d_in[6];
    const float* s2w0 = (const float*)d_in[7];  const float* s2b0 = (const float*)d_in[8];
    const float* s2w1 = (const float*)d_in[9];  const float* s2b1 = (const float*)d_in[10];
    const float* s2w2 = (const float*)d_in[11]; const float* s2b2 = (const float*)d_in[12];
    const float* s3w0 = (const float*)d_in[13]; const float* s3b0 = (const float*)d_in[14];
    const float* s3w1 = (const float*)d_in[15]; const float* s3b1 = (const float*)d_in[16];
    const float* s3w2 = (const float*)d_in[17]; const float* s3b2 = (const float*)d_in[18];
    const float* w_mu = (const float*)d_in[19]; const float* b_mu = (const float*)d_in[20];
    const float* w_lv = (const float*)d_in[21]; const float* b_lv = (const float*)d_in[22];
    float* out = (float*)d_out;

    static cudaStream_t s1 = nullptr, s2 = nullptr;
    static cudaEvent_t eF[4] = {nullptr, nullptr, nullptr, nullptr};
    static cudaEvent_t eK = nullptr, eL = nullptr;
    if (!s1) {
        cudaStreamCreateWithFlags(&s1, cudaStreamNonBlocking);
        cudaStreamCreateWithFlags(&s2, cudaStreamNonBlocking);
        for (int i = 0; i < 4; ++i) cudaEventCreateWithFlags(&eF[i], cudaEventDisableTiming);
        cudaEventCreateWithFlags(&eK, cudaEventDisableTiming);
        cudaEventCreateWithFlags(&eL, cudaEventDisableTiming);
        cudaFuncSetAttribute(fps_kernel, cudaFuncAttributeMaxDynamicSharedMemorySize, 50 * 1024);
        cudaFuncSetAttribute(knn_kernel, cudaFuncAttributeMaxDynamicSharedMemorySize, 20 * 1024);
    }

    // ---- fps0 in 4 chunks on default stream; knn0 chunks pipelined on s1 ----
    const int CH0 = M1 / 4;   // 512 centers per chunk
    for (int k = 0; k < 4; ++k) {
        fps_kernel<<<BATCH, 512, NPTS * 3 * sizeof(float)>>>(pos, 0, NPTS, M1,
                                                             k * CH0, (k + 1) * CH0);
        cudaEventRecord(eF[k], 0);
        cudaStreamWaitEvent(s1, eF[k], 0);
        knn_kernel<<<BATCH * CH0, 128, 1024 * sizeof(u64), s1>>>(
            pos, 0, NPTS, M1, 0.04f, 6400.0f, 1024, k * CH0, CH0);
    }
    cudaEventRecord(eK, s1);

    // ---- level-1 sampling on s2 (hidden under knn0/sa1) ----
    cudaStreamWaitEvent(s2, eF[3], 0);
    fps_kernel<<<BATCH, 512, M1 * 3 * sizeof(float), s2>>>(pos, 1, M1, M2, 0, M2);
    knn_kernel<<<BATCH * M2, 128, 2048 * sizeof(u64), s2>>>(
        pos, 1, M1, M2, 0.16f, 1600.0f, 2048, 0, M2);
    cudaEventRecord(eL, s2);

    // ---- main chain ----
    cudaStreamWaitEvent(0, eK, 0);
    sa1_kernel<<<BATCH * M1, 128>>>(pos, s1w0, s1b0, s1w1, s1b1, s1w2, s1b2);
    cudaStreamWaitEvent(0, eL, 0);
    sa2_kernel<<<BATCH * M2, 128>>>(s2w0, s2b0, s2w1, s2b1, s2w2, s2b2);
    sa3_kernel<<<BATCH * 64, 128>>>(s3w0, s3b0, s3w1, s3b1, s3w2, s3b2);
    head_kernel<<<BATCH, 32>>>(w_mu, b_mu, w_lv, b_lv, out);
}

// round 17
// speedup vs baseline: 1.0608x; 1.0608x over previous
#include <cuda_runtime.h>
#include <cstdint>
#include <math.h>

#define BATCH 8
#define NPTS  4096
#define M1    2048
#define M2    512
#define KNB   64
#define TIE_CAP 128

typedef unsigned long long u64;

// ----------------------------------------------------------------------------
// Scratch (device globals; no allocations allowed)
// ----------------------------------------------------------------------------
static __device__ __align__(16) float    g_cent1[BATCH * M1 * 3];
static __device__ int      g_nbr1 [BATCH * M1 * KNB];
static __device__ int      g_cnt1 [BATCH * M1];
static __device__ __align__(16) float    g_x1   [BATCH * M1 * 64];
static __device__ __align__(16) float    g_cent2[BATCH * M2 * 3];
static __device__ int      g_nbr2 [BATCH * M2 * KNB];
static __device__ int      g_cnt2 [BATCH * M2];
static __device__ __align__(16) float    g_x2   [BATCH * M2 * 128];
static __device__ unsigned g_featEnc[BATCH * 512];

// ----------------------------------------------------------------------------
// Helpers
// ----------------------------------------------------------------------------
__device__ __forceinline__ float d2_ref(float dx, float dy, float dz) {
    // XLA-style fused emission of sum((p-c)**2) over size-3 axis
    return __fmaf_rn(dz, dz, __fmaf_rn(dy, dy, __fmul_rn(dx, dx)));
}

__device__ __forceinline__ unsigned encf(float f) {
    unsigned u = __float_as_uint(f);
    return (u & 0x80000000u) ? ~u : (u | 0x80000000u);
}
__device__ __forceinline__ float decf(unsigned u) {
    return (u & 0x80000000u) ? __uint_as_float(u & 0x7FFFFFFFu) : __uint_as_float(~u);
}

// packed f32x2 FMA: acc = a*b + acc (two independent IEEE fp32 FMAs)
__device__ __forceinline__ void ffma2(u64& acc, u64 a, u64 b) {
    asm("fma.rn.f32x2 %0, %1, %2, %0;" : "+l"(acc) : "l"(a), "l"(b));
}
__device__ __forceinline__ u64 bcast2(float f) {
    u64 r;
    asm("mov.b64 %0, {%1, %1};" : "=l"(r) : "f"(f));
    return r;
}
__device__ __forceinline__ void unpack2(u64 p, float& lo, float& hi) {
    asm("mov.b64 {%0, %1}, %2;" : "=f"(lo), "=f"(hi) : "l"(p));
}

// ----------------------------------------------------------------------------
// FPS: one block (512 thr) per batch. REDUX-based argmax, one barrier/iter.
// ----------------------------------------------------------------------------
__global__ void fps_kernel(const float* __restrict__ pos_ext, int level, int N, int M)
{
    extern __shared__ float spos[];  // N*3 floats
    __shared__ u64 wred[2][16];

    const float* srcbase = (level == 0) ? pos_ext : g_cent1;
    float* cent_out      = (level == 0) ? g_cent1 : g_cent2;

    const int b = blockIdx.x, tid = threadIdx.x;
    const int nt = 512;
    const float* P = srcbase + (size_t)b * N * 3;
    for (int i = tid; i < N * 3; i += nt) spos[i] = P[i];
    __syncthreads();

    float lx[8], ly[8], lz[8], ld[8];
    const int KP = N / nt;              // 8 (level0) or 4 (level1)
    #pragma unroll
    for (int k = 0; k < 8; ++k) {
        if (k < KP) {
            int p = tid + k * nt;
            lx[k] = spos[p*3]; ly[k] = spos[p*3+1]; lz[k] = spos[p*3+2];
        }
        ld[k] = __int_as_float(0x7f800000);  // +inf
    }

    const int lane = tid & 31, warp = tid >> 5;
    int fidx = 0;

    for (int t = 0; t < M; ++t) {
        float cx = spos[fidx*3], cy = spos[fidx*3+1], cz = spos[fidx*3+2];
        if (tid == 0) {
            int o = (b * M + t) * 3;
            cent_out[o] = cx; cent_out[o+1] = cy; cent_out[o+2] = cz;
        }
        unsigned bb = 0u; int bi = 0;
        #pragma unroll
        for (int k = 0; k < 8; ++k) {
            if (k < KP) {
                int p = tid + k * nt;
                float d  = d2_ref(lx[k]-cx, ly[k]-cy, lz[k]-cz);
                float nd = fminf(ld[k], d);
                ld[k] = nd;
                unsigned bits = __float_as_uint(nd);   // nd >= 0 -> uint order == float order
                if (bits > bb) { bb = bits; bi = p; }  // ascending p -> min idx on tie
            }
        }
        unsigned m    = __reduce_max_sync(0xFFFFFFFFu, bb);
        unsigned cand = (bb == m) ? (unsigned)bi : 0xFFFFFFFFu;
        unsigned widx = __reduce_min_sync(0xFFFFFFFFu, cand);
        if (lane == 0) wred[t & 1][warp] = (((u64)m) << 32) | widx;
        __syncthreads();
        u64 kk = (lane < 16) ? wred[t & 1][lane] : 0ULL;
        unsigned hi = (unsigned)(kk >> 32), lo = (unsigned)kk;
        unsigned m2    = __reduce_max_sync(0xFFFFFFFFu, hi);
        unsigned cand2 = (hi == m2) ? lo : 0xFFFFFFFFu;
        fidx = (int)__reduce_min_sync(0xFFFFFFFFu, cand2);
    }
}

// ----------------------------------------------------------------------------
// KNN: radius-limited 64 smallest, one block (128 thr) per center.
// float4-vectorized scan + histogram cutoff-selection; bitonic fallback.
// Level 1 additionally zeroes g_featEnc[bm] (grid == BATCH*512).
// ----------------------------------------------------------------------------
struct __align__(16) KnnShared {
    int scnt, osel, tcnt, sT, sN1;
    int hist[256];
    u64 tie[TIE_CAP];
};

__global__ __launch_bounds__(128) void knn_kernel(
    const float* __restrict__ pos_ext, int level, int N, int M, float R2,
    float binscale, int CAP)
{
    extern __shared__ u64 keys[];  // CAP entries
    __shared__ KnnShared S;

    const float* pts     = (level == 0) ? pos_ext : g_cent1;
    const float* centers = (level == 0) ? g_cent1 : g_cent2;
    int* nbr             = (level == 0) ? g_nbr1  : g_nbr2;
    int* cnt             = (level == 0) ? g_cnt1  : g_cnt2;

    const int bm = blockIdx.x;      // b*M + m
    const int b  = bm / M;
    const int tid = threadIdx.x, nt = 128;
    if (level == 1 && tid == 0) g_featEnc[bm] = 0u;

    const float* P = pts + (size_t)b * N * 3;
    const float cx = centers[bm*3], cy = centers[bm*3+1], cz = centers[bm*3+2];

    if (tid == 0) { S.scnt = 0; S.osel = 0; S.tcnt = 0; }
    for (int i = tid; i < 256; i += nt) S.hist[i] = 0;
    __syncthreads();

    // vectorized scan: 4 points per thread-iteration via 3x LDG.128
    const float4* P4 = reinterpret_cast<const float4*>(P);
    const int NG = N >> 2;
    for (int g = tid; g < NG; g += nt) {
        float4 A = __ldg(P4 + g*3 + 0);
        float4 B = __ldg(P4 + g*3 + 1);
        float4 Cv = __ldg(P4 + g*3 + 2);
        float px[4] = {A.x, A.w, B.z, Cv.y};
        float py[4] = {A.y, B.x, B.w, Cv.z};
        float pz[4] = {A.z, B.y, Cv.x, Cv.w};
        #pragma unroll
        for (int k = 0; k < 4; ++k) {
            float d2 = d2_ref(px[k]-cx, py[k]-cy, pz[k]-cz);
            if (d2 <= R2) {
                int q = atomicAdd(&S.scnt, 1);
                if (q < CAP) {
                    keys[q] = (((u64)__float_as_uint(d2)) << 32) | (unsigned)(4*g + k);
                    int bin = (int)(d2 * binscale); if (bin > 255) bin = 255;
                    atomicAdd(&S.hist[bin], 1);
                }
            }
        }
    }
    __syncthreads();
    int C = S.scnt; if (C > CAP) C = CAP;
    const int KO = (C < KNB) ? C : KNB;

    if (C <= KNB) {
        for (int k = tid; k < KNB; k += nt)
            nbr[(size_t)bm * KNB + k] = (k < C) ? (int)(unsigned)keys[k] : 0;
        if (tid == 0) cnt[bm] = KO;
        return;
    }

    // cutoff bin T: first bin with cumulative count >= 64
    const int warp = tid >> 5, lane = tid & 31;
    if (warp == 0) {
        int base8 = lane * 8;
        int h[8]; int s = 0;
        #pragma unroll
        for (int k = 0; k < 8; ++k) { h[k] = S.hist[base8 + k]; s += h[k]; }
        int Ssc = s;
        #pragma unroll
        for (int o = 1; o < 32; o <<= 1) {
            int v = __shfl_up_sync(0xFFFFFFFFu, Ssc, o);
            if (lane >= o) Ssc += v;
        }
        unsigned bal = __ballot_sync(0xFFFFFFFFu, Ssc >= KNB);
        int L = __ffs(bal) - 1;
        int Sprev = __shfl_up_sync(0xFFFFFFFFu, Ssc, 1);
        if (lane == L) {
            int cum = (L > 0) ? Sprev : 0;
            int T = base8, n1v = cum;
            #pragma unroll
            for (int k = 0; k < 8; ++k) {
                if (cum + h[k] >= KNB) { T = base8 + k; n1v = cum; break; }
                cum += h[k];
            }
            S.sT = T; S.sN1 = n1v;
        }
    }
    __syncthreads();
    const int T = S.sT, n1 = S.sN1, k2 = KNB - n1;

    for (int q = tid; q < C; q += nt) {
        u64 key = keys[q];
        float d2 = __uint_as_float((unsigned)(key >> 32));
        int bin = (int)(d2 * binscale); if (bin > 255) bin = 255;
        if (bin < T) {
            int o = atomicAdd(&S.osel, 1);
            nbr[(size_t)bm * KNB + o] = (int)(unsigned)key;
        } else if (bin == T) {
            int tq = atomicAdd(&S.tcnt, 1);
            if (tq < TIE_CAP) S.tie[tq] = key;
        }
    }
    __syncthreads();

    if (S.tcnt <= TIE_CAP) {
        const int t = S.tcnt;
        for (int e = tid; e < t; e += nt) {
            u64 me = S.tie[e];
            int rank = 0;
            for (int f = 0; f < t; ++f) rank += (S.tie[f] < me);
            if (rank < k2) nbr[(size_t)bm * KNB + n1 + rank] = (int)(unsigned)me;
        }
    } else {
        // fallback: full bitonic sort (never expected on this data)
        int Pow = 1; while (Pow < C) Pow <<= 1;
        for (int i = C + tid; i < Pow; i += nt) keys[i] = ~0ULL;
        __syncthreads();
        for (int size = 2; size <= Pow; size <<= 1) {
            for (int stride = size >> 1; stride > 0; stride >>= 1) {
                for (int t2 = tid; t2 < (Pow >> 1); t2 += nt) {
                    int lo = (t2 << 1) - (t2 & (stride - 1));
                    int hi = lo + stride;
                    u64 a = keys[lo], c2 = keys[hi];
                    bool asc = ((lo & size) == 0);
                    if ((a > c2) == asc) { keys[lo] = c2; keys[hi] = a; }
                }
                __syncthreads();
            }
        }
        for (int k = tid; k < KNB; k += nt)
            nbr[(size_t)bm * KNB + k] = (int)(unsigned)keys[k];
    }
    if (tid == 0) cnt[bm] = KNB;
}

// ----------------------------------------------------------------------------
// Templated MLP layer on duplicated-pair feature buffers (row-major mapping,
// per-i LDS.64 feature broadcast). Measured-best variant.
// ----------------------------------------------------------------------------
template<int DIN, int DOUT, bool RELUDUP, int R>
__device__ __forceinline__ void mlpD(const u64* __restrict__ Fin, void* __restrict__ Fout,
                                     const float* __restrict__ w, const float* __restrict__ bias,
                                     int rows)
{
    constexpr int JB = DOUT / 4;     // power of two
    const int tid = threadIdx.x;
    const int total = (rows / R) * JB;
    for (int it = tid; it < total; it += 128) {
        const int np = it / JB;
        const int j  = (it - np * JB) << 2;
        const u64* f0 = Fin + (np * R) * DIN;
        ulonglong2 b2 = *reinterpret_cast<const ulonglong2*>(bias + j);
        u64 accL[R], accH[R];
        #pragma unroll
        for (int r = 0; r < R; ++r) { accL[r] = b2.x; accH[r] = b2.y; }
        #pragma unroll 4
        for (int i = 0; i < DIN; ++i) {
            ulonglong2 wv = __ldg(reinterpret_cast<const ulonglong2*>(w + i * DOUT + j));
            #pragma unroll
            for (int r = 0; r < R; ++r) {
                u64 u = f0[r * DIN + i];
                ffma2(accL[r], wv.x, u);
                ffma2(accH[r], wv.y, u);
            }
        }
        if (RELUDUP) {
            u64* out = (u64*)Fout;
            #pragma unroll
            for (int r = 0; r < R; ++r) {
                u64* o = out + (np * R + r) * DOUT + j;
                float x, y;
                unpack2(accL[r], x, y);
                o[0] = bcast2(fmaxf(x, 0.f)); o[1] = bcast2(fmaxf(y, 0.f));
                unpack2(accH[r], x, y);
                o[2] = bcast2(fmaxf(x, 0.f)); o[3] = bcast2(fmaxf(y, 0.f));
            }
        } else {
            float* out = (float*)Fout;
            #pragma unroll
            for (int r = 0; r < R; ++r)
                *reinterpret_cast<ulonglong2*>(out + (np * R + r) * DOUT + j) =
                    make_ulonglong2(accL[r], accH[r]);
        }
    }
}

// ----------------------------------------------------------------------------
// SA1: per-center MLP(3->32->32->64) over 64 neighbors + masked max.
// C == 64 fast path: fully unrolled max reduction.
// ----------------------------------------------------------------------------
__global__ __launch_bounds__(128) void sa1_kernel(
    const float* __restrict__ pos,
    const float* __restrict__ w0, const float* __restrict__ b0,
    const float* __restrict__ w1, const float* __restrict__ b1,
    const float* __restrict__ w2, const float* __restrict__ b2)
{
    __shared__ __align__(16) u64 F0[64 * 3];
    __shared__ __align__(16) u64 FA[64 * 32];    // L0 out dup; final plain f32 (64x64)
    __shared__ __align__(16) u64 FB[64 * 32];    // L1 out dup
    const int bm = blockIdx.x;      // b*M1 + m
    const int b  = bm >> 11;
    const int tid = threadIdx.x;
    const int C = g_cnt1[bm];

    if (tid < 64) {
        int n = tid;
        float rx = 0.f, ry = 0.f, rz = 0.f;
        if (n < C) {
            int q = g_nbr1[(size_t)bm * KNB + n];
            const float* pp = pos + ((size_t)b * NPTS + q) * 3;
            rx = pp[0] - g_cent1[bm*3];
            ry = pp[1] - g_cent1[bm*3+1];
            rz = pp[2] - g_cent1[bm*3+2];
        }
        F0[n*3] = bcast2(rx); F0[n*3+1] = bcast2(ry); F0[n*3+2] = bcast2(rz);
    }
    __syncthreads();
    mlpD<3, 32, true, 4>(F0, FA, w0, b0, 64); __syncthreads();
    mlpD<32, 32, true, 4>(FA, FB, w1, b1, 64); __syncthreads();
    mlpD<32, 64, false, 4>(FB, FA, w2, b2, 64); __syncthreads();
    const float* FC = (const float*)FA;
    if (C == KNB) {
        for (int j = tid; j < 64; j += 128) {
            float m = FC[j];
            #pragma unroll
            for (int n = 1; n < KNB; ++n) m = fmaxf(m, FC[n*64 + j]);
            g_x1[(size_t)bm * 64 + j] = m;
        }
    } else {
        for (int j = tid; j < 64; j += 128) {
            float m = FC[j];
            for (int n = 1; n < C; ++n) m = fmaxf(m, FC[n*64 + j]);
            g_x1[(size_t)bm * 64 + j] = m;
        }
    }
}

// ----------------------------------------------------------------------------
// SA2: per-center MLP(67->64->64->128) over 64 neighbors + masked max.
// Row-chunked (32 rows); C == 64 fast path with unrolled gather + max.
// ----------------------------------------------------------------------------
__global__ __launch_bounds__(128) void sa2_kernel(
    const float* __restrict__ w0, const float* __restrict__ b0,
    const float* __restrict__ w1, const float* __restrict__ b1,
    const float* __restrict__ w2, const float* __restrict__ b2)
{
    __shared__ __align__(16) u64 bufA[32 * 67];  // in dup (67); L1 out dup (64)
    __shared__ __align__(16) u64 bufB[32 * 64];  // L0 out dup (64); final plain f32 (32x128)
    __shared__ float srel[64 * 3];
    __shared__ int   sq[64];
    const int bm = blockIdx.x;      // b*M2 + m
    const int b  = bm >> 9;
    const int tid = threadIdx.x;
    const int C = g_cnt2[bm];
    const bool full = (C == KNB);

    if (tid < 64) {
        int n = tid;
        int q = 0; float rx = 0.f, ry = 0.f, rz = 0.f;
        if (n < C) {
            q = g_nbr2[(size_t)bm * KNB + n];
            const float* pp = g_cent1 + ((size_t)b * M1 + q) * 3;
            rx = pp[0] - g_cent2[bm*3];
            ry = pp[1] - g_cent2[bm*3+1];
            rz = pp[2] - g_cent2[bm*3+2];
        }
        sq[n] = q; srel[n*3] = rx; srel[n*3+1] = ry; srel[n*3+2] = rz;
    }
    __syncthreads();

    float m = -__int_as_float(0x7f800000);   // -inf; C >= 1 always
    #pragma unroll
    for (int chunk = 0; chunk < 2; ++chunk) {
        const int r0 = chunk * 32;
        if (r0 >= C) break;
        if (full) {
            for (int e = tid; e < 32 * 64; e += 128) {
                int n = e >> 6, i = e & 63;
                bufA[n*67 + i] = bcast2(g_x1[((size_t)b * M1 + sq[r0 + n]) * 64 + i]);
            }
            if (tid < 96) {
                int n = tid / 3, c = tid - n * 3;
                bufA[n*67 + 64 + c] = bcast2(srel[(r0 + n)*3 + c]);
            }
        } else {
            for (int e = tid; e < 32 * 64; e += 128) {
                int n = e >> 6, i = e & 63;
                int g = r0 + n;
                bufA[n*67 + i] = (g < C) ? bcast2(g_x1[((size_t)b * M1 + sq[g]) * 64 + i]) : 0ULL;
            }
            if (tid < 96) {
                int n = tid / 3, c = tid - n * 3;
                int g = r0 + n;
                bufA[n*67 + 64 + c] = (g < C) ? bcast2(srel[g*3 + c]) : 0ULL;
            }
        }
        __syncthreads();
        mlpD<67, 64, true, 4>(bufA, bufB, w0, b0, 32); __syncthreads();
        mlpD<64, 64, true, 4>(bufB, bufA, w1, b1, 32); __syncthreads();
        mlpD<64, 128, false, 4>(bufA, bufB, w2, b2, 32); __syncthreads();
        const float* FC = (const float*)bufB;
        if (tid < 128) {
            if (full) {
                float mm = m;
                #pragma unroll
                for (int n = 0; n < 32; ++n) mm = fmaxf(mm, FC[n*128 + tid]);
                m = mm;
            } else {
                int nv = C - r0; if (nv > 32) nv = 32;
                float mm = m;
                for (int n = 0; n < nv; ++n) mm = fmaxf(mm, FC[n*128 + tid]);
                m = mm;
            }
        }
        __syncthreads();
    }
    g_x2[(size_t)bm * 128 + tid] = m;
}

// ----------------------------------------------------------------------------
// SA3 + global max pool: MLP(131->128->256->512) per point, atomic-max pool.
// ----------------------------------------------------------------------------
__global__ __launch_bounds__(128) void sa3_kernel(
    const float* __restrict__ w0, const float* __restrict__ b0,
    const float* __restrict__ w1, const float* __restrict__ b1,
    const float* __restrict__ w2, const float* __restrict__ b2)
{
    __shared__ __align__(16) u64 bufA[8 * 256];   // in dup (131); L1 out dup (256)
    __shared__ __align__(16) u64 bufB[8 * 256];   // L0 out dup (128); final plain f32 (8x512)
    const int b  = blockIdx.x >> 6;             // 64 blocks per batch
    const int m0 = (blockIdx.x & 63) * 8;
    const int tid = threadIdx.x;

    for (int e = tid; e < 8 * 128; e += 128) {
        int n = e >> 7, i = e & 127;
        bufA[n*131 + i] = bcast2(g_x2[((size_t)b * M2 + m0 + n) * 128 + i]);
    }
    if (tid < 24) {
        int n = tid / 3, c = tid - n * 3;
        bufA[n*131 + 128 + c] = bcast2(g_cent2[((size_t)b * M2 + m0 + n) * 3 + c]);
    }
    __syncthreads();
    mlpD<131, 128, true, 2>(bufA, bufB, w0, b0, 8); __syncthreads();
    mlpD<128, 256, true, 4>(bufB, bufA, w1, b1, 8); __syncthreads();
    mlpD<256, 512, false, 4>(bufA, bufB, w2, b2, 8); __syncthreads();
    const float* FC = (const float*)bufB;
    for (int j = tid; j < 512; j += 128) {
        float m = FC[j];
        #pragma unroll
        for (int n = 1; n < 8; ++n) m = fmaxf(m, FC[n*512 + j]);
        atomicMax(&g_featEnc[b * 512 + j], encf(m));
    }
}

// ----------------------------------------------------------------------------
// Head: mu/logvar linear + reparameterization (partitionable threefry).
// ----------------------------------------------------------------------------
__device__ __forceinline__ uint32_t rotl32(uint32_t x, int r) { return (x << r) | (x >> (32 - r)); }

__device__ __forceinline__ void threefry2x32(uint32_t k0, uint32_t k1, uint32_t& x0, uint32_t& x1)
{
    uint32_t ks0 = k0, ks1 = k1, ks2 = k0 ^ k1 ^ 0x1BD11BDAu;
    const int R0[4] = {13, 15, 26, 6};
    const int R1[4] = {17, 29, 16, 24};
    x0 += ks0; x1 += ks1;
    #pragma unroll
    for (int i = 0; i < 5; ++i) {
        #pragma unroll
        for (int rr = 0; rr < 4; ++rr) {
            int r = (i & 1) ? R1[rr] : R0[rr];
            x0 += x1; x1 = rotl32(x1, r); x1 ^= x0;
        }
        uint32_t a = (i % 3 == 0) ? ks1 : ((i % 3 == 1) ? ks2 : ks0);
        uint32_t c = (i % 3 == 0) ? ks2 : ((i % 3 == 1) ? ks0 : ks1);
        x0 += a; x1 += c + (uint32_t)(i + 1);
    }
}

__global__ void head_kernel(const float* __restrict__ w_mu, const float* __restrict__ b_mu,
                            const float* __restrict__ w_lv, const float* __restrict__ b_lv,
                            float* __restrict__ out)
{
    __shared__ float feat[512];
    const int b = blockIdx.x, tid = threadIdx.x;  // 32 threads
    for (int i = tid; i < 512; i += 32) feat[i] = decf(g_featEnc[b * 512 + i]);
    __syncthreads();

    const int j = tid;
    float mu = __ldg(b_mu + j), lv = __ldg(b_lv + j);
    #pragma unroll 4
    for (int i = 0; i < 512; ++i) {
        float f = feat[i];
        mu = fmaf(f, __ldg(w_mu + i * 32 + j), mu);
        lv = fmaf(f, __ldg(w_lv + i * 32 + j), lv);
    }

    int e = b * 32 + j;
    uint32_t x0 = 0u, x1 = (uint32_t)e;
    threefry2x32(0u, 42u, x0, x1);
    uint32_t y = x0 ^ x1;

    float u01 = __uint_as_float((y >> 9) | 0x3F800000u) - 1.0f;
    const float lo = -0.99999994f;
    float u = fmaxf(lo, __fmaf_rn(u01, 2.0f, lo));
    float eps = 1.41421356f * erfinvf(u);

    float z = mu + eps * expf(0.5f * lv);
    out[b * 32 + j]        = z;
    out[256 + b * 32 + j]  = mu;
    out[512 + b * 32 + j]  = lv;
}

// ----------------------------------------------------------------------------
// Launch:
//   main:  fps0 -> knn0 -> sa1 -> [join] -> sa2 -> sa3 -> head
//   side:  [wait fps0] fps1 -> knn1 (knn1 zeroes g_featEnc)
// ----------------------------------------------------------------------------
extern "C" void kernel_launch(void* const* d_in, const int* in_sizes, int n_in,
                              void* d_out, int out_size)
{
    (void)in_sizes; (void)n_in; (void)out_size;
    const float* pos  = (const float*)d_in[0];
    const float* s1w0 = (const float*)d_in[1];  const float* s1b0 = (const float*)d_in[2];
    const float* s1w1 = (const float*)d_in[3];  const float* s1b1 = (const float*)d_in[4];
    const float* s1w2 = (const float*)d_in[5];  const float* s1b2 = (const float*)d_in[6];
    const float* s2w0 = (const float*)d_in[7];  const float* s2b0 = (const float*)d_in[8];
    const float* s2w1 = (const float*)d_in[9];  const float* s2b1 = (const float*)d_in[10];
    const float* s2w2 = (const float*)d_in[11]; const float* s2b2 = (const float*)d_in[12];
    const float* s3w0 = (const float*)d_in[13]; const float* s3b0 = (const float*)d_in[14];
    const float* s3w1 = (const float*)d_in[15]; const float* s3b1 = (const float*)d_in[16];
    const float* s3w2 = (const float*)d_in[17]; const float* s3b2 = (const float*)d_in[18];
    const float* w_mu = (const float*)d_in[19]; const float* b_mu = (const float*)d_in[20];
    const float* w_lv = (const float*)d_in[21]; const float* b_lv = (const float*)d_in[22];
    float* out = (float*)d_out;

    static cudaStream_t s_side = nullptr;
    static cudaEvent_t evA = nullptr, evB = nullptr;
    if (!s_side) {
        cudaStreamCreateWithFlags(&s_side, cudaStreamNonBlocking);
        cudaEventCreateWithFlags(&evA, cudaEventDisableTiming);
        cudaEventCreateWithFlags(&evB, cudaEventDisableTiming);
        cudaFuncSetAttribute(fps_kernel, cudaFuncAttributeMaxDynamicSharedMemorySize, 50 * 1024);
        cudaFuncSetAttribute(knn_kernel, cudaFuncAttributeMaxDynamicSharedMemorySize, 20 * 1024);
    }

    // ---- main: level-0 chain ----
    fps_kernel<<<BATCH, 512, NPTS * 3 * sizeof(float)>>>(pos, 0, NPTS, M1);
    cudaEventRecord(evA, 0);
    knn_kernel<<<BATCH * M1, 128, 1024 * sizeof(u64)>>>(pos, 0, NPTS, M1, 0.04f, 6400.0f, 1024);
    sa1_kernel<<<BATCH * M1, 128>>>(pos, s1w0, s1b0, s1w1, s1b1, s1w2, s1b2);

    // ---- side: level-1 sampling overlapping knn0/sa1 ----
    cudaStreamWaitEvent(s_side, evA, 0);
    fps_kernel<<<BATCH, 512, M1 * 3 * sizeof(float), s_side>>>(pos, 1, M1, M2);
    knn_kernel<<<BATCH * M2, 128, 2048 * sizeof(u64), s_side>>>(pos, 1, M1, M2, 0.16f, 1600.0f, 2048);
    cudaEventRecord(evB, s_side);

    // ---- join, then level-2 chain ----
    cudaStreamWaitEvent(0, evB, 0);
    sa2_kernel<<<BATCH * M2, 128>>>(s2w0, s2b0, s2w1, s2b1, s2w2, s2b2);
    sa3_kernel<<<BATCH * 64, 128>>>(s3w0, s3b0, s3w1, s3b1, s3w2, s3b2);
    head_kernel<<<BATCH, 32>>>(w_mu, b_mu, w_lv, b_lv, out);
}